// round 1
// baseline (speedup 1.0000x reference)
#include <cuda_runtime.h>
#include <cstdint>

#define DK 128
#define NB 4096
#define NC 16384

#define BM 128
#define BN 128
#define BK 32
#define SSTR 36   // smem row stride in floats: (4*row+col) mod 32 distinct -> conflict-free frags

// Scratch (allocation-free per harness rules)
__device__ float g_xn[(size_t)NB * DK];
__device__ float g_pn[(size_t)NC * DK];
__device__ float g_xs[NB];
__device__ float g_ps[NC];

__device__ __forceinline__ float to_tf32(float x) {
    float r;
    asm("cvt.rna.tf32.f32 %0, %1;" : "=f"(r) : "f"(x));
    return r;
}

// One block per row, 128 threads. which==0 -> inputs->g_xn/g_xs, which==1 -> kernel->g_pn/g_ps
__global__ void normalize_rows(const float* __restrict__ v, int which) {
    int row = blockIdx.x;
    int t = threadIdx.x;
    float x = v[(size_t)row * DK + t];
    float sq = x * x;
#pragma unroll
    for (int o = 16; o > 0; o >>= 1) sq += __shfl_xor_sync(0xffffffffu, sq, o);
    __shared__ float red[4];
    if ((t & 31) == 0) red[t >> 5] = sq;
    __syncthreads();
    float s = red[0] + red[1] + red[2] + red[3];
    float m = fmaxf(s, 1e-12f);
    float scale = 3.0f * rsqrtf(m);
    float xn = to_tf32(x * scale);
    if (which == 0) {
        g_xn[(size_t)row * DK + t] = xn;
        if (t == 0) g_xs[row] = 9.0f * (s / m);
    } else {
        g_pn[(size_t)row * DK + t] = xn;
        if (t == 0) g_ps[row] = 9.0f * (s / m);
    }
}

__global__ void __launch_bounds__(256, 1) nca_gemm(float* __restrict__ out) {
    __shared__ float sA[BM * SSTR];
    __shared__ float sB[BN * SSTR];
    __shared__ float sXS[BM];
    __shared__ float sPS[BN];

    const int tid = threadIdx.x;
    const int bN = blockIdx.x;   // 0..127
    const int bM = blockIdx.y;   // 0..31
    const int warpId = tid >> 5;
    const int lane = tid & 31;
    const int warpM = warpId >> 2;  // 0..1
    const int warpN = warpId & 3;   // 0..3
    const int grp = lane >> 2;      // 0..7
    const int tg = lane & 3;        // 0..3

    const float* gA = g_xn + (size_t)bM * BM * DK;
    const float* gB = g_pn + (size_t)bN * BN * DK;

    if (tid < 128) sXS[tid] = g_xs[bM * BM + tid];
    else           sPS[tid - 128] = g_ps[bN * BN + (tid - 128)];

    float acc[4][4][4];
#pragma unroll
    for (int mi = 0; mi < 4; mi++)
#pragma unroll
        for (int ni = 0; ni < 4; ni++)
#pragma unroll
            for (int r = 0; r < 4; r++) acc[mi][ni][r] = 0.0f;

    // Each thread loads 4 float4 per tile per matrix. i = t4*256 + tid over 1024 float4s.
    float4 bufA[4], bufB[4];
#pragma unroll
    for (int t4 = 0; t4 < 4; t4++) {
        int i = t4 * 256 + tid;
        int r = i >> 3;
        int c4 = (i & 7) * 4;
        bufA[t4] = *reinterpret_cast<const float4*>(gA + (size_t)r * DK + c4);
        bufB[t4] = *reinterpret_cast<const float4*>(gB + (size_t)r * DK + c4);
    }

#pragma unroll
    for (int kc = 0; kc < 4; kc++) {
#pragma unroll
        for (int t4 = 0; t4 < 4; t4++) {
            int i = t4 * 256 + tid;
            int r = i >> 3;
            int c4 = (i & 7) * 4;
            *reinterpret_cast<float4*>(&sA[r * SSTR + c4]) = bufA[t4];
            *reinterpret_cast<float4*>(&sB[r * SSTR + c4]) = bufB[t4];
        }
        __syncthreads();

        if (kc < 3) {
            int k0n = (kc + 1) * BK;
#pragma unroll
            for (int t4 = 0; t4 < 4; t4++) {
                int i = t4 * 256 + tid;
                int r = i >> 3;
                int c4 = (i & 7) * 4;
                bufA[t4] = *reinterpret_cast<const float4*>(gA + (size_t)r * DK + k0n + c4);
                bufB[t4] = *reinterpret_cast<const float4*>(gB + (size_t)r * DK + k0n + c4);
            }
        }

#pragma unroll
        for (int ks = 0; ks < 4; ks++) {
            int k0 = ks * 8;
            float a[4][4];
#pragma unroll
            for (int mi = 0; mi < 4; mi++) {
                int rb = warpM * 64 + mi * 16;
                a[mi][0] = sA[(rb + grp) * SSTR + k0 + tg];
                a[mi][1] = sA[(rb + grp + 8) * SSTR + k0 + tg];
                a[mi][2] = sA[(rb + grp) * SSTR + k0 + tg + 4];
                a[mi][3] = sA[(rb + grp + 8) * SSTR + k0 + tg + 4];
            }
            float b[4][2];
#pragma unroll
            for (int ni = 0; ni < 4; ni++) {
                int cb = warpN * 32 + ni * 8;
                b[ni][0] = sB[(cb + grp) * SSTR + k0 + tg];
                b[ni][1] = sB[(cb + grp) * SSTR + k0 + tg + 4];
            }
#pragma unroll
            for (int mi = 0; mi < 4; mi++) {
#pragma unroll
                for (int ni = 0; ni < 4; ni++) {
                    asm("mma.sync.aligned.m16n8k8.row.col.f32.tf32.tf32.f32 "
                        "{%0,%1,%2,%3},{%4,%5,%6,%7},{%8,%9},{%0,%1,%2,%3};"
                        : "+f"(acc[mi][ni][0]), "+f"(acc[mi][ni][1]),
                          "+f"(acc[mi][ni][2]), "+f"(acc[mi][ni][3])
                        : "r"(__float_as_uint(a[mi][0])), "r"(__float_as_uint(a[mi][1])),
                          "r"(__float_as_uint(a[mi][2])), "r"(__float_as_uint(a[mi][3])),
                          "r"(__float_as_uint(b[ni][0])), "r"(__float_as_uint(b[ni][1])));
                }
            }
        }
        __syncthreads();
    }

    // Epilogue: out = xs + ps - 2*dot
#pragma unroll
    for (int mi = 0; mi < 4; mi++) {
        int r0 = warpM * 64 + mi * 16 + grp;
        size_t grow0 = (size_t)(bM * BM + r0) * NC;
        size_t grow1 = (size_t)(bM * BM + r0 + 8) * NC;
        float xs0 = sXS[r0];
        float xs1 = sXS[r0 + 8];
#pragma unroll
        for (int ni = 0; ni < 4; ni++) {
            int c0 = warpN * 32 + ni * 8 + tg * 2;
            int gcol = bN * BN + c0;
            float p0 = sPS[c0];
            float p1 = sPS[c0 + 1];
            float2 v0, v1;
            v0.x = xs0 + p0 - 2.0f * acc[mi][ni][0];
            v0.y = xs0 + p1 - 2.0f * acc[mi][ni][1];
            v1.x = xs1 + p0 - 2.0f * acc[mi][ni][2];
            v1.y = xs1 + p1 - 2.0f * acc[mi][ni][3];
            *reinterpret_cast<float2*>(out + grow0 + gcol) = v0;
            *reinterpret_cast<float2*>(out + grow1 + gcol) = v1;
        }
    }
}

extern "C" void kernel_launch(void* const* d_in, const int* in_sizes, int n_in,
                              void* d_out, int out_size) {
    const float* inputs = (const float*)d_in[0];   // [4096, 128]
    const float* kern   = (const float*)d_in[1];   // [16384, 128]
    float* out = (float*)d_out;                    // [4096, 16384]

    normalize_rows<<<NB, 128>>>(inputs, 0);
    normalize_rows<<<NC, 128>>>(kern, 1);

    dim3 grid(NC / BN, NB / BM);  // (128, 32)
    nca_gemm<<<grid, 256>>>(out);
}

// round 5
// speedup vs baseline: 1.9181x; 1.9181x over previous
#include <cuda_runtime.h>
#include <cuda_fp16.h>
#include <cstdint>

#define DK 128
#define NB 4096
#define NC 16384
#define TM 128
#define TN 256

// dynamic smem layout (bytes)
#define A_OFF 0         // 128 rows x 256B (fp16 K=128)  = 32 KB
#define B_OFF 32768     // 256 rows x 256B               = 64 KB
#define XS_OFF 98304    // 128 floats
#define PS_OFF 98816    // 256 floats
#define SMEM_BYTES 99840

// Scratch (allocation-free per harness rules)
__device__ __half g_xn[(size_t)NB * DK];
__device__ __half g_pn[(size_t)NC * DK];
__device__ float g_xs[NB];
__device__ float g_ps[NC];

__device__ __forceinline__ uint32_t smem_u32(const void* p) {
    return (uint32_t)__cvta_generic_to_shared(p);
}

// swizzled byte offset for (row, 16B-chunk u): conflict-free LDSM + cp.async
__device__ __forceinline__ uint32_t swz(int row, int u) {
    return (uint32_t)(row * 256 + ((u ^ (row & 7)) << 4));
}

__device__ __forceinline__ void cp16(uint32_t dst, const __half* src) {
    asm volatile("cp.async.cg.shared.global [%0], [%1], 16;\n"
                 :: "r"(dst), "l"(__cvta_generic_to_global(src)) : "memory");
}

#define LDSM4(r0, r1, r2, r3, addr)                                          \
    asm volatile("ldmatrix.sync.aligned.m8n8.x4.shared.b16 {%0,%1,%2,%3}, [%4];" \
                 : "=r"(r0), "=r"(r1), "=r"(r2), "=r"(r3) : "r"(addr))

#define MMA16816(d, a, b0, b1)                                               \
    asm volatile("mma.sync.aligned.m16n8k16.row.col.f32.f16.f16.f32 "        \
                 "{%0,%1,%2,%3},{%4,%5,%6,%7},{%8,%9},{%0,%1,%2,%3};"        \
                 : "+f"(d[0]), "+f"(d[1]), "+f"(d[2]), "+f"(d[3])            \
                 : "r"(a[0]), "r"(a[1]), "r"(a[2]), "r"(a[3]), "r"(b0), "r"(b1))

// ---------------- normalize: one warp per row (which: 0=inputs, 1=kernel) ----------------
__global__ void normalize_rows(const float* __restrict__ v, int which) {
    int wid = threadIdx.x >> 5;
    int lane = threadIdx.x & 31;
    int row = blockIdx.x * 8 + wid;
    float4 x = *reinterpret_cast<const float4*>(v + (size_t)row * DK + lane * 4);
    float sq = x.x * x.x + x.y * x.y + x.z * x.z + x.w * x.w;
#pragma unroll
    for (int o = 16; o > 0; o >>= 1) sq += __shfl_xor_sync(0xffffffffu, sq, o);
    float m = fmaxf(sq, 1e-12f);
    float scale = 3.0f * rsqrtf(m);
    __half2 h0 = __floats2half2_rn(x.x * scale, x.y * scale);
    __half2 h1 = __floats2half2_rn(x.z * scale, x.w * scale);
    uint2 st;
    st.x = *reinterpret_cast<uint32_t*>(&h0);
    st.y = *reinterpret_cast<uint32_t*>(&h1);
    __half* dst = which ? g_pn : g_xn;
    float* sums = which ? g_ps : g_xs;
    *reinterpret_cast<uint2*>(dst + (size_t)row * DK + lane * 4) = st;
    if (lane == 0) sums[row] = 9.0f * (sq / m);
}

// ---------------- GEMM + fused epilogue (fp16 mma.sync + ldmatrix) ----------------
__global__ void __launch_bounds__(256, 1) nca_gemm(float* __restrict__ out) {
    extern __shared__ char smem[];
    float* smf = reinterpret_cast<float*>(smem);
    const int tid = threadIdx.x;
    const int wid = tid >> 5;
    const int lane = tid & 31;
    const int bN = blockIdx.x;   // 0..63
    const int bM = blockIdx.y;   // 0..31
    const int warpM = wid & 1;   // 0..1  (64 rows each)
    const int warpN = wid >> 1;  // 0..3  (64 cols each)
    const uint32_t sbase = smem_u32(smem);

    const __half* gA = g_xn + (size_t)bM * TM * DK;
    const __half* gB = g_pn + (size_t)bN * TN * DK;

    // K split into two halves; one commit group each for load/compute overlap
#pragma unroll
    for (int h = 0; h < 2; h++) {
#pragma unroll
        for (int i = tid; i < (TM * 8); i += 256) {       // 128 rows x 8 chunks
            int r = i >> 3, u = (i & 7) | (h << 3);
            cp16(sbase + A_OFF + swz(r, u), gA + (size_t)r * DK + u * 8);
        }
#pragma unroll
        for (int i = tid; i < (TN * 8); i += 256) {       // 256 rows x 8 chunks
            int r = i >> 3, u = (i & 7) | (h << 3);
            cp16(sbase + B_OFF + swz(r, u), gB + (size_t)r * DK + u * 8);
        }
        asm volatile("cp.async.commit_group;\n" ::: "memory");
    }

    if (tid < TM) smf[XS_OFF / 4 + tid] = g_xs[bM * TM + tid];
    smf[PS_OFF / 4 + tid] = g_ps[bN * TN + tid];

    float acc[4][8][4];
#pragma unroll
    for (int mi = 0; mi < 4; mi++)
#pragma unroll
        for (int ni = 0; ni < 8; ni++)
#pragma unroll
            for (int r = 0; r < 4; r++) acc[mi][ni][r] = 0.0f;

    const int mseg = lane >> 3;            // which 8x8 matrix this lane addresses
    const int mrow8 = lane & 7;
    const int a_row_base = warpM * 64 + ((mseg & 1) << 3) + mrow8;
    const int a_u_add = mseg >> 1;
    const int b_row_base = warpN * 64 + ((mseg >> 1) << 3) + mrow8;
    const int b_u_add = mseg & 1;

    asm volatile("cp.async.wait_group 1;\n" ::: "memory");
    __syncthreads();

#pragma unroll
    for (int half = 0; half < 2; half++) {
        if (half == 1) {
            asm volatile("cp.async.wait_group 0;\n" ::: "memory");
            __syncthreads();
        }
#pragma unroll
        for (int ks = half * 4; ks < half * 4 + 4; ks++) {
            const int ub = ks * 2;
            uint32_t a[4][4], b[4][4];
#pragma unroll
            for (int mi = 0; mi < 4; mi++) {
                int row = a_row_base + mi * 16;
                LDSM4(a[mi][0], a[mi][1], a[mi][2], a[mi][3],
                      sbase + A_OFF + swz(row, ub + a_u_add));
            }
#pragma unroll
            for (int nj = 0; nj < 4; nj++) {
                int row = b_row_base + nj * 16;
                LDSM4(b[nj][0], b[nj][1], b[nj][2], b[nj][3],
                      sbase + B_OFF + swz(row, ub + b_u_add));
            }
#pragma unroll
            for (int mi = 0; mi < 4; mi++) {
#pragma unroll
                for (int ni = 0; ni < 8; ni++) {
                    MMA16816(acc[mi][ni], a[mi], b[ni >> 1][(ni & 1) * 2],
                             b[ni >> 1][(ni & 1) * 2 + 1]);
                }
            }
        }
    }

    // Epilogue: out = xs + ps - 2*dot, straight from accumulators
    const int lg = lane >> 2;   // row group 0..7
    const int tg = lane & 3;    // col pair 0..3
#pragma unroll
    for (int mi = 0; mi < 4; mi++) {
        int r = warpM * 64 + mi * 16 + lg;
        float xs0 = smf[XS_OFF / 4 + r];
        float xs1 = smf[XS_OFF / 4 + r + 8];
        size_t g0 = (size_t)(bM * TM + r) * NC + bN * TN;
        size_t g1 = g0 + (size_t)8 * NC;
#pragma unroll
        for (int ni = 0; ni < 8; ni++) {
            int c = warpN * 64 + ni * 8 + (tg << 1);
            float p0 = smf[PS_OFF / 4 + c];
            float p1 = smf[PS_OFF / 4 + c + 1];
            float2 v0, v1;
            v0.x = xs0 + p0 - 2.0f * acc[mi][ni][0];
            v0.y = xs0 + p1 - 2.0f * acc[mi][ni][1];
            v1.x = xs1 + p0 - 2.0f * acc[mi][ni][2];
            v1.y = xs1 + p1 - 2.0f * acc[mi][ni][3];
            *reinterpret_cast<float2*>(out + g0 + c) = v0;
            *reinterpret_cast<float2*>(out + g1 + c) = v1;
        }
    }
}

extern "C" void kernel_launch(void* const* d_in, const int* in_sizes, int n_in,
                              void* d_out, int out_size) {
    const float* inputs = (const float*)d_in[0];   // [4096, 128]
    const float* kern   = (const float*)d_in[1];   // [16384, 128]
    float* out = (float*)d_out;                    // [4096, 16384]

    normalize_rows<<<NB / 8, 256>>>(inputs, 0);
    normalize_rows<<<NC / 8, 256>>>(kern, 1);

    cudaFuncSetAttribute(nca_gemm, cudaFuncAttributeMaxDynamicSharedMemorySize, SMEM_BYTES);
    dim3 grid(NC / TN, NB / TM);  // (64, 32)
    nca_gemm<<<grid, 256, SMEM_BYTES>>>(out);
}